// round 7
// baseline (speedup 1.0000x reference)
#include <cuda_runtime.h>
#include <math.h>

#define BB 64
#define TT 512
#define II 256
#define HH 512
#define CC 128

// Scratch (static device allocations are allowed; cudaMalloc is not)
__device__ float g_gates[(size_t)TT * BB * 4 * HH];   // [t][b][4H]  256 MB
__device__ float g_hs[(size_t)TT * BB * HH];          // [t][b][H]    64 MB
__device__ float g_h[2][BB * HH];                     // ping-pong h state

// Flag-array barriers: 4 batch groups x 64 CTA slots. Slot stores (t+1).
__device__ unsigned int g_flags[4][64];
// One-shot full-grid barrier (replay-safe, generation counting)
__device__ unsigned int g_bar_count;
__device__ unsigned int g_bar_gen;

__device__ __forceinline__ float sigmoidf_(float x) {
    return 1.0f / (1.0f + expf(-x));
}

// Packed dual-FMA: acc(lo,hi) += a(lo,hi) * b(lo,hi)   (ptxas never auto-fuses)
__device__ __forceinline__ void ffma2(unsigned long long& acc,
                                      unsigned long long a,
                                      unsigned long long b) {
    asm("fma.rn.f32x2 %0, %1, %2, %0;" : "+l"(acc) : "l"(a), "l"(b));
}

__device__ __forceinline__ unsigned long long pack2(float x) {
    unsigned long long r;
    asm("mov.b64 %0, {%1, %1};" : "=l"(r) : "f"(x));
    return r;
}

__device__ __forceinline__ float pairsum(unsigned long long v) {
    float2 f = *(float2*)&v;
    return f.x + f.y;
}

// Volatile L2 load/store for barrier flags (compiler must not hoist/CSE).
__device__ __forceinline__ unsigned int ldcg_u32v(const unsigned int* p) {
    unsigned int v;
    asm volatile("ld.global.cg.u32 %0, [%1];" : "=r"(v) : "l"(p));
    return v;
}
__device__ __forceinline__ void stcg_u32v(unsigned int* p, unsigned int v) {
    asm volatile("st.global.cg.u32 [%0], %1;" :: "l"(p), "r"(v) : "memory");
}

// ---------------------------------------------------------------------------
// Phase 1: G[t][b][n] = x[b][t][:] . W_ih[n][:] + b_ih[n] + b_hh[n]
// 128x128 tile, BK=8, 256 threads, 8x8 per thread; inner loop in fma.rn.f32x2.
// ---------------------------------------------------------------------------
__global__ void __launch_bounds__(256) gates_gemm(
    const float* __restrict__ x,
    const float* __restrict__ W_ih,
    const float* __restrict__ b_ih,
    const float* __restrict__ b_hh)
{
    __shared__ float As[8][128];
    __shared__ float Bs[8][128];

    const int n0 = blockIdx.x * 128;
    const int m0 = blockIdx.y * 128;
    const int tid = threadIdx.x;
    const int tx = tid & 15;
    const int ty = tid >> 4;

    unsigned long long acc2[8][4];
#pragma unroll
    for (int i = 0; i < 8; i++)
#pragma unroll
        for (int j = 0; j < 4; j++) acc2[i][j] = 0ull;

    const int lr = tid >> 1;
    const int lk = (tid & 1) * 4;

    for (int k0 = 0; k0 < II; k0 += 8) {
        {
            float4 v = *(const float4*)(x + (size_t)(m0 + lr) * II + k0 + lk);
            As[lk + 0][lr] = v.x; As[lk + 1][lr] = v.y;
            As[lk + 2][lr] = v.z; As[lk + 3][lr] = v.w;
        }
        {
            float4 v = *(const float4*)(W_ih + (size_t)(n0 + lr) * II + k0 + lk);
            Bs[lk + 0][lr] = v.x; Bs[lk + 1][lr] = v.y;
            Bs[lk + 2][lr] = v.z; Bs[lk + 3][lr] = v.w;
        }
        __syncthreads();
#pragma unroll
        for (int k = 0; k < 8; k++) {
            float a[8];
            float4 a0 = *(const float4*)&As[k][ty * 4];
            float4 a1 = *(const float4*)&As[k][64 + ty * 4];
            ulonglong2 bp0 = *(const ulonglong2*)&Bs[k][tx * 4];
            ulonglong2 bp1 = *(const ulonglong2*)&Bs[k][64 + tx * 4];
            a[0]=a0.x; a[1]=a0.y; a[2]=a0.z; a[3]=a0.w;
            a[4]=a1.x; a[5]=a1.y; a[6]=a1.z; a[7]=a1.w;
#pragma unroll
            for (int i = 0; i < 8; i++) {
                unsigned long long a2 = pack2(a[i]);
                ffma2(acc2[i][0], a2, bp0.x);
                ffma2(acc2[i][1], a2, bp0.y);
                ffma2(acc2[i][2], a2, bp1.x);
                ffma2(acc2[i][3], a2, bp1.y);
            }
        }
        __syncthreads();
    }

#pragma unroll
    for (int i = 0; i < 8; i++) {
        int m = m0 + (i >> 2) * 64 + ty * 4 + (i & 3);
        int bb = m >> 9;
        int tt = m & 511;
        size_t row = ((size_t)tt * BB + bb) * (4 * HH);
#pragma unroll
        for (int j2 = 0; j2 < 4; j2++) {
            float2 f = *(float2*)&acc2[i][j2];
            int jlo = j2 * 2;
            int n0c = n0 + (jlo >> 2) * 64 + tx * 4 + (jlo & 3);
            g_gates[row + n0c]     = f.x + b_ih[n0c]     + b_hh[n0c];
            g_gates[row + n0c + 1] = f.y + b_ih[n0c + 1] + b_hh[n0c + 1];
        }
    }
}

// ---------------------------------------------------------------------------
// Phase 2: persistent recurrence with intra-CTA warp specialization by
// batch group. 128 CTAs x 256 threads. CTA i owns j-slice jg=i>>1 (8 units);
// warps 0-3 (half A) run batch group 2*(i&1), warps 4-7 (half B) run group
// 2*(i&1)+1. Halves share the W smem (8u x 4g x 512 = 64 KB) but have
// independent stage buffers, named barriers (1/2) and 64-CTA flag barriers,
// so one half's compute hides the other's barrier/staging latency.
// ---------------------------------------------------------------------------
#define W_PITCH 129                 // float4 pitch per weight row
#define H_PITCH 516                 // float pitch per staged h row
#define WSM_F4  (32 * W_PITCH)      // 32 weight rows (8 units x 4 gates)
#define SMEM_RECUR ((WSM_F4 * 16) + 2 * (16 * H_PITCH * 4))   // 132096 B

__global__ void __launch_bounds__(256) lstm_recur(const float* __restrict__ W_hh)
{
    extern __shared__ float smem[];
    float4* Ws4  = (float4*)smem;                     // [(g*8+u)*W_PITCH + k4]
    float*  hsmA = smem + WSM_F4 * 4;
    float*  hsmB = hsmA + 16 * H_PITCH;

    const int tid  = threadIdx.x;
    const int half = tid >> 7;          // 0 = warps 0-3, 1 = warps 4-7
    const int htid = tid & 127;
    const int bl   = htid & 15;         // batch lane 0..15
    const int jl   = htid >> 4;         // unit lane  0..7
    const int cta  = blockIdx.x;
    const int jg   = cta >> 1;          // 0..63
    const int j0   = jg * 8;
    const int bg   = (cta & 1) * 2 + half;   // this half's batch group 0..3
    const int b    = bg * 16 + bl;
    const int j    = j0 + jl;
    const int barid = 1 + half;
    float* hsm = half ? hsmB : hsmA;
    unsigned int* myflags = g_flags[bg];

    // Cooperative W_hh load: 32 rows (g*8+u) x 128 float4.
    for (int idx = tid; idx < 32 * 128; idx += 256) {
        int r  = idx >> 7;              // g*8 + u
        int k4 = idx & 127;
        int g  = r >> 3;
        int u  = r & 7;
        Ws4[r * W_PITCH + k4] =
            *(const float4*)(W_hh + ((size_t)(g * HH + j0 + u)) * HH + k4 * 4);
    }

    // Reset this half's flag slot and h state (fresh every graph replay).
    if (htid == 0) stcg_u32v(&myflags[jg], 0u);
    __stcg(&g_h[0][b * HH + j], 0.0f);
    float c = 0.0f;

    // One-shot full-grid barrier (atomic gen, replay-safe). Also orders the
    // smem W loads (via its syncthreads) and the flag/h resets (via fences).
    __threadfence();
    __syncthreads();
    if (tid == 0) {
        unsigned int my = *((volatile unsigned int*)&g_bar_gen);
        unsigned int arrived = atomicAdd(&g_bar_count, 1u);
        if (arrived == (unsigned)gridDim.x - 1) {
            atomicExch(&g_bar_count, 0u);
            __threadfence();
            atomicAdd(&g_bar_gen, 1u);
        } else {
            while (*((volatile unsigned int*)&g_bar_gen) == my) { __nanosleep(32); }
        }
        __threadfence();
    }
    __syncthreads();

    const ulonglong2* Wi = (const ulonglong2*)(Ws4 + ( 0 + jl) * W_PITCH);
    const ulonglong2* Wf = (const ulonglong2*)(Ws4 + ( 8 + jl) * W_PITCH);
    const ulonglong2* Wg = (const ulonglong2*)(Ws4 + (16 + jl) * W_PITCH);
    const ulonglong2* Wo = (const ulonglong2*)(Ws4 + (24 + jl) * W_PITCH);
    const ulonglong2* Hr = (const ulonglong2*)(hsm + bl * H_PITCH);

    for (int t = 0; t < TT; t++) {
        // Stage h[t] for this half's 16 batches into smem.
        const float* hsrc = &g_h[t & 1][(bg * 16) * HH];
#pragma unroll
        for (int i = 0; i < 16; i++) {
            int idx  = i * 128 + htid;        // 0..2047 float4s
            int brow = idx >> 7;
            int k4   = idx & 127;
            float4 v = __ldcg((const float4*)(hsrc + (size_t)brow * HH) + k4);
            *(float4*)(hsm + brow * H_PITCH + k4 * 4) = v;
        }

        // Prefetch precomputed gate inputs (DRAM; latency hidden below).
        const float* xg = &g_gates[((size_t)t * BB + b) * (4 * HH) + j];
        float xi  = __ldcg(xg);
        float xf  = __ldcg(xg + HH);
        float xgg = __ldcg(xg + 2 * HH);
        float xo  = __ldcg(xg + 3 * HH);

        asm volatile("bar.sync %0, 128;" :: "r"(barid) : "memory");  // stage done

        unsigned long long ai = 0ull, af = 0ull, ag = 0ull, ao = 0ull;
#pragma unroll 8
        for (int k4 = 0; k4 < 128; k4++) {
            ulonglong2 h2 = Hr[k4];
            ulonglong2 wi = Wi[k4];
            ulonglong2 wf = Wf[k4];
            ulonglong2 wg = Wg[k4];
            ulonglong2 wo = Wo[k4];
            ffma2(ai, h2.x, wi.x); ffma2(ai, h2.y, wi.y);
            ffma2(af, h2.x, wf.x); ffma2(af, h2.y, wf.y);
            ffma2(ag, h2.x, wg.x); ffma2(ag, h2.y, wg.y);
            ffma2(ao, h2.x, wo.x); ffma2(ao, h2.y, wo.y);
        }

        float gi = sigmoidf_(xi  + pairsum(ai));
        float gf = sigmoidf_(xf  + pairsum(af));
        float gg = tanhf    (xgg + pairsum(ag));
        float go = sigmoidf_(xo  + pairsum(ao));
        c = gf * c + gi * gg;
        float hv = go * tanhf(c);
        __stcg(&g_h[(t + 1) & 1][b * HH + j], hv);

        // ---- arrive: fence own stores, half-sync, signal flag ----
        __threadfence();
        asm volatile("bar.sync %0, 128;" :: "r"(barid) : "memory");
        if (htid == 0) stcg_u32v(&myflags[jg], (unsigned int)(t + 1));

        // History store rides the barrier-poll window (no step consumer).
        g_hs[((size_t)t * BB + b) * HH + j] = hv;

        // ---- wait: warp 0 of the half polls all 64 slots of its group ----
        if (htid < 32) {
            unsigned int tgt = (unsigned int)(t + 1);
            while (true) {
                unsigned int f0 = ldcg_u32v(&myflags[htid]);
                unsigned int f1 = ldcg_u32v(&myflags[htid + 32]);
                bool ok = (f0 >= tgt) && (f1 >= tgt);
                if (__all_sync(0xffffffffu, ok)) break;
                __nanosleep(20);
            }
            __threadfence();
        }
        asm volatile("bar.sync %0, 128;" :: "r"(barid) : "memory");
    }
}

// ---------------------------------------------------------------------------
// Phase 3: out[b][t][c] = hs[t][b][:] . W_fc[c][:] + b_fc[c]  (unchanged)
// ---------------------------------------------------------------------------
__global__ void __launch_bounds__(256) fc_gemm(
    const float* __restrict__ W_fc,
    const float* __restrict__ b_fc,
    float* __restrict__ out)
{
    __shared__ float As[8][128];
    __shared__ float Bs[8][128];

    const int m0 = blockIdx.x * 128;
    const int tid = threadIdx.x;
    const int tx = tid & 15;
    const int ty = tid >> 4;

    float acc[8][8];
#pragma unroll
    for (int i = 0; i < 8; i++)
#pragma unroll
        for (int j = 0; j < 8; j++) acc[i][j] = 0.0f;

    const int lr = tid >> 1;
    const int lk = (tid & 1) * 4;

    for (int k0 = 0; k0 < HH; k0 += 8) {
        {
            float4 v = *(const float4*)(g_hs + (size_t)(m0 + lr) * HH + k0 + lk);
            As[lk + 0][lr] = v.x; As[lk + 1][lr] = v.y;
            As[lk + 2][lr] = v.z; As[lk + 3][lr] = v.w;
        }
        {
            float4 v = *(const float4*)(W_fc + (size_t)lr * HH + k0 + lk);
            Bs[lk + 0][lr] = v.x; Bs[lk + 1][lr] = v.y;
            Bs[lk + 2][lr] = v.z; Bs[lk + 3][lr] = v.w;
        }
        __syncthreads();
#pragma unroll
        for (int k = 0; k < 8; k++) {
            float a[8], b[8];
            float4 a0 = *(const float4*)&As[k][ty * 4];
            float4 a1 = *(const float4*)&As[k][64 + ty * 4];
            float4 b0 = *(const float4*)&Bs[k][tx * 4];
            float4 b1 = *(const float4*)&Bs[k][64 + tx * 4];
            a[0]=a0.x; a[1]=a0.y; a[2]=a0.z; a[3]=a0.w;
            a[4]=a1.x; a[5]=a1.y; a[6]=a1.z; a[7]=a1.w;
            b[0]=b0.x; b[1]=b0.y; b[2]=b0.z; b[3]=b0.w;
            b[4]=b1.x; b[5]=b1.y; b[6]=b1.z; b[7]=b1.w;
#pragma unroll
            for (int i = 0; i < 8; i++)
#pragma unroll
                for (int j = 0; j < 8; j++)
                    acc[i][j] = fmaf(a[i], b[j], acc[i][j]);
        }
        __syncthreads();
    }

#pragma unroll
    for (int i = 0; i < 8; i++) {
        int m = m0 + (i >> 2) * 64 + ty * 4 + (i & 3);
        int bb = m & 63;
        int tt = m >> 6;
        size_t orow = ((size_t)bb * TT + tt) * CC;
#pragma unroll
        for (int j = 0; j < 8; j++) {
            int cc = (j >> 2) * 64 + tx * 4 + (j & 3);
            out[orow + cc] = acc[i][j] + b_fc[cc];
        }
    }
}

// ---------------------------------------------------------------------------
extern "C" void kernel_launch(void* const* d_in, const int* in_sizes, int n_in,
                              void* d_out, int out_size)
{
    const float* x    = (const float*)d_in[0];
    const float* W_ih = (const float*)d_in[1];
    const float* W_hh = (const float*)d_in[2];
    const float* b_ih = (const float*)d_in[3];
    const float* b_hh = (const float*)d_in[4];
    const float* W_fc = (const float*)d_in[5];
    const float* b_fc = (const float*)d_in[6];
    float* out = (float*)d_out;

    cudaFuncSetAttribute(lstm_recur,
                         cudaFuncAttributeMaxDynamicSharedMemorySize,
                         SMEM_RECUR);

    dim3 g1(4 * HH / 128, (BB * TT) / 128);   // (16, 256)
    gates_gemm<<<g1, 256>>>(x, W_ih, b_ih, b_hh);

    lstm_recur<<<128, 256, SMEM_RECUR>>>(W_hh);   // 128 CTAs, co-resident

    fc_gemm<<<(BB * TT) / 128, 256>>>(W_fc, b_fc, out);
}

// round 8
// speedup vs baseline: 1.4446x; 1.4446x over previous
#include <cuda_runtime.h>
#include <math.h>

#define BB 64
#define TT 512
#define II 256
#define HH 512
#define CC 128

// Scratch (static device allocations are allowed; cudaMalloc is not)
__device__ float g_gates[(size_t)TT * BB * 4 * HH];   // [t][b][4H]  256 MB
__device__ float g_hs[(size_t)TT * BB * HH];          // [t][b][H]    64 MB
__device__ float g_h[2][BB * HH];                     // ping-pong h state

// Flag-array barriers: 4 batch groups x 32 CTA slots, each slot on its own
// 128-byte line (no atomic serialization, no shared-line contention).
__device__ unsigned int g_flags[4][32][32];
// One-shot full-grid barrier (replay-safe, generation counting) for init.
__device__ unsigned int g_bar_count;
__device__ unsigned int g_bar_gen;

__device__ __forceinline__ float sigmoidf_(float x) {
    return 1.0f / (1.0f + expf(-x));
}

// Packed dual-FMA: acc(lo,hi) += a(lo,hi) * b(lo,hi)   (ptxas never auto-fuses)
__device__ __forceinline__ void ffma2(unsigned long long& acc,
                                      unsigned long long a,
                                      unsigned long long b) {
    asm("fma.rn.f32x2 %0, %1, %2, %0;" : "+l"(acc) : "l"(a), "l"(b));
}

__device__ __forceinline__ unsigned long long pack2(float x) {
    unsigned long long r;
    asm("mov.b64 %0, {%1, %1};" : "=l"(r) : "f"(x));
    return r;
}

__device__ __forceinline__ float pairsum(unsigned long long v) {
    float2 f = *(float2*)&v;
    return f.x + f.y;
}

// Volatile L2 load/store for barrier flags (compiler must not hoist/CSE).
__device__ __forceinline__ unsigned int ldcg_u32v(const unsigned int* p) {
    unsigned int v;
    asm volatile("ld.global.cg.u32 %0, [%1];" : "=r"(v) : "l"(p));
    return v;
}
__device__ __forceinline__ void stcg_u32v(unsigned int* p, unsigned int v) {
    asm volatile("st.global.cg.u32 [%0], %1;" :: "l"(p), "r"(v) : "memory");
}

// ---------------------------------------------------------------------------
// Phase 1: G[t][b][n] = x[b][t][:] . W_ih[n][:] + b_ih[n] + b_hh[n]
// 128x128 tile, BK=8, 256 threads, 8x8 per thread; inner loop in fma.rn.f32x2.
// ---------------------------------------------------------------------------
__global__ void __launch_bounds__(256) gates_gemm(
    const float* __restrict__ x,
    const float* __restrict__ W_ih,
    const float* __restrict__ b_ih,
    const float* __restrict__ b_hh)
{
    __shared__ float As[8][128];
    __shared__ float Bs[8][128];

    const int n0 = blockIdx.x * 128;
    const int m0 = blockIdx.y * 128;
    const int tid = threadIdx.x;
    const int tx = tid & 15;
    const int ty = tid >> 4;

    unsigned long long acc2[8][4];
#pragma unroll
    for (int i = 0; i < 8; i++)
#pragma unroll
        for (int j = 0; j < 4; j++) acc2[i][j] = 0ull;

    const int lr = tid >> 1;
    const int lk = (tid & 1) * 4;

    for (int k0 = 0; k0 < II; k0 += 8) {
        {
            float4 v = *(const float4*)(x + (size_t)(m0 + lr) * II + k0 + lk);
            As[lk + 0][lr] = v.x; As[lk + 1][lr] = v.y;
            As[lk + 2][lr] = v.z; As[lk + 3][lr] = v.w;
        }
        {
            float4 v = *(const float4*)(W_ih + (size_t)(n0 + lr) * II + k0 + lk);
            Bs[lk + 0][lr] = v.x; Bs[lk + 1][lr] = v.y;
            Bs[lk + 2][lr] = v.z; Bs[lk + 3][lr] = v.w;
        }
        __syncthreads();
#pragma unroll
        for (int k = 0; k < 8; k++) {
            float a[8];
            float4 a0 = *(const float4*)&As[k][ty * 4];
            float4 a1 = *(const float4*)&As[k][64 + ty * 4];
            ulonglong2 bp0 = *(const ulonglong2*)&Bs[k][tx * 4];
            ulonglong2 bp1 = *(const ulonglong2*)&Bs[k][64 + tx * 4];
            a[0]=a0.x; a[1]=a0.y; a[2]=a0.z; a[3]=a0.w;
            a[4]=a1.x; a[5]=a1.y; a[6]=a1.z; a[7]=a1.w;
#pragma unroll
            for (int i = 0; i < 8; i++) {
                unsigned long long a2 = pack2(a[i]);
                ffma2(acc2[i][0], a2, bp0.x);
                ffma2(acc2[i][1], a2, bp0.y);
                ffma2(acc2[i][2], a2, bp1.x);
                ffma2(acc2[i][3], a2, bp1.y);
            }
        }
        __syncthreads();
    }

#pragma unroll
    for (int i = 0; i < 8; i++) {
        int m = m0 + (i >> 2) * 64 + ty * 4 + (i & 3);
        int bb = m >> 9;
        int tt = m & 511;
        size_t row = ((size_t)tt * BB + bb) * (4 * HH);
#pragma unroll
        for (int j2 = 0; j2 < 4; j2++) {
            float2 f = *(float2*)&acc2[i][j2];
            int jlo = j2 * 2;
            int n0c = n0 + (jlo >> 2) * 64 + tx * 4 + (jlo & 3);
            g_gates[row + n0c]     = f.x + b_ih[n0c]     + b_hh[n0c];
            g_gates[row + n0c + 1] = f.y + b_ih[n0c + 1] + b_hh[n0c + 1];
        }
    }
}

// ---------------------------------------------------------------------------
// Phase 2: persistent recurrence, 2-D sharded (exact R5 shape).
// Grid = 128 CTAs: blockIdx -> (bg 0..3, jg 0..31). CTA owns batches
// bg*16..+15 and units jg*16..+15 (256 threads, one (b, j) cell each).
// Weights in padded smem for the whole kernel; h staged to smem per step.
// ONLY change vs R5: the per-step barrier is a flag-array barrier scoped to
// the 32 CTAs of the same batch group (no atomic serialization), and the
// final step skips the barrier.
// ---------------------------------------------------------------------------
#define W_PITCH 129                 // float4 units per (jl,gate) row (pad vs 128)
#define H_PITCH 516                 // floats per staged h row (pad vs 512)
#define WSM_F4  (16 * 4 * W_PITCH)              // float4 count for weights
#define SMEM_RECUR ((WSM_F4 * 16) + (16 * H_PITCH * 4))   // bytes

__global__ void __launch_bounds__(256) lstm_recur(const float* __restrict__ W_hh)
{
    extern __shared__ float smem[];
    float4* Ws4 = (float4*)smem;                      // [ (jl*4+gate)*W_PITCH + k4 ]
    float*  hsm = smem + WSM_F4 * 4;                  // [ bl*H_PITCH + k ]

    const int tid = threadIdx.x;
    const int bl  = tid & 15;          // batch-lane 0..15
    const int jl  = tid >> 4;          // unit-lane  0..15
    const int bg  = blockIdx.x & 3;
    const int jg  = blockIdx.x >> 2;   // 0..31 = slot in this bg's barrier
    const int b   = bg * 16 + bl;
    const int j   = jg * 16 + jl;
    const int j0  = jg * 16;

    // Load this CTA's W_hh slice: rows (gate*H + j0+u), u=0..15. 8192 float4s.
    for (int idx = tid; idx < 16 * 4 * 128; idx += 256) {
        int u   = idx >> 9;            // 0..15
        int rem = idx & 511;
        int g   = rem >> 7;            // 0..3
        int k4  = rem & 127;
        Ws4[(u * 4 + g) * W_PITCH + k4] =
            *(const float4*)(W_hh + ((size_t)(g * HH + j0 + u)) * HH + k4 * 4);
    }

    // init read-buffer h to 0 and reset our flag slot (fresh every replay)
    __stcg(&g_h[0][b * HH + j], 0.0f);
    if (tid == 0) stcg_u32v(&g_flags[bg][jg][0], 0u);
    float c = 0.0f;

    // One-shot full-grid barrier: orders h-zero + flag resets across ALL CTAs
    // before any flag-wait can observe them. (Atomic cost paid once only.)
    __threadfence();
    __syncthreads();
    if (tid == 0) {
        unsigned int my = *((volatile unsigned int*)&g_bar_gen);
        unsigned int arrived = atomicAdd(&g_bar_count, 1u);
        if (arrived == (unsigned)gridDim.x - 1) {
            atomicExch(&g_bar_count, 0u);
            __threadfence();
            atomicAdd(&g_bar_gen, 1u);
        } else {
            while (*((volatile unsigned int*)&g_bar_gen) == my) { __nanosleep(32); }
        }
        __threadfence();
    }
    __syncthreads();

    const ulonglong2* Wi = (const ulonglong2*)(Ws4 + (jl * 4 + 0) * W_PITCH);
    const ulonglong2* Wf = (const ulonglong2*)(Ws4 + (jl * 4 + 1) * W_PITCH);
    const ulonglong2* Wg = (const ulonglong2*)(Ws4 + (jl * 4 + 2) * W_PITCH);
    const ulonglong2* Wo = (const ulonglong2*)(Ws4 + (jl * 4 + 3) * W_PITCH);
    const ulonglong2* Hr = (const ulonglong2*)(hsm + bl * H_PITCH);

    for (int t = 0; t < TT; t++) {
        // Stage h[t] for this CTA's 16 batches into smem.
        const float* hsrc = &g_h[t & 1][(bg * 16) * HH];
#pragma unroll
        for (int i = 0; i < 8; i++) {
            int idx  = i * 256 + tid;          // 0..2047 float4s
            int brow = idx >> 7;               // 0..15
            int k4   = idx & 127;
            float4 v = __ldcg((const float4*)(hsrc + (size_t)brow * HH) + k4);
            *(float4*)(hsm + brow * H_PITCH + k4 * 4) = v;
        }

        // Prefetch precomputed gate inputs (DRAM; latency hidden below).
        const float* xg = &g_gates[((size_t)t * BB + b) * (4 * HH) + j];
        float xi  = __ldcg(xg);
        float xf  = __ldcg(xg + HH);
        float xgg = __ldcg(xg + 2 * HH);
        float xo  = __ldcg(xg + 3 * HH);

        __syncthreads();   // staged h visible

        unsigned long long ai = 0ull, af = 0ull, ag = 0ull, ao = 0ull;
#pragma unroll 8
        for (int k4 = 0; k4 < 128; k4++) {
            ulonglong2 h2 = Hr[k4];
            ulonglong2 wi = Wi[k4];
            ulonglong2 wf = Wf[k4];
            ulonglong2 wg = Wg[k4];
            ulonglong2 wo = Wo[k4];
            ffma2(ai, h2.x, wi.x); ffma2(ai, h2.y, wi.y);
            ffma2(af, h2.x, wf.x); ffma2(af, h2.y, wf.y);
            ffma2(ag, h2.x, wg.x); ffma2(ag, h2.y, wg.y);
            ffma2(ao, h2.x, wo.x); ffma2(ao, h2.y, wo.y);
        }

        float gi = sigmoidf_(xi  + pairsum(ai));
        float gf = sigmoidf_(xf  + pairsum(af));
        float gg = tanhf    (xgg + pairsum(ag));
        float go = sigmoidf_(xo  + pairsum(ao));
        c = gf * c + gi * gg;
        float hv = go * tanhf(c);
        __stcg(&g_h[(t + 1) & 1][b * HH + j], hv);

        if (t == TT - 1) {
            // no consumer of h[T]; just emit history and exit loop
            g_hs[((size_t)t * BB + b) * HH + j] = hv;
            break;
        }

        // ---- flag-array group barrier (32 CTAs of this bg) ----
        __threadfence();                 // h stcg visible in L2
        __syncthreads();                 // all 256 threads' stores fenced
        if (tid == 0) stcg_u32v(&g_flags[bg][jg][0], (unsigned int)(t + 1));

        // History store rides the poll window (no step consumer).
        g_hs[((size_t)t * BB + b) * HH + j] = hv;

        if (tid < 32) {
            unsigned int tgt = (unsigned int)(t + 1);
            while (true) {
                unsigned int f = ldcg_u32v(&g_flags[bg][tid][0]);
                if (__all_sync(0xffffffffu, f >= tgt)) break;
                __nanosleep(20);
            }
            __threadfence();             // acquire
        }
        __syncthreads();
    }
}

// ---------------------------------------------------------------------------
// Phase 3: out[b][t][c] = hs[t][b][:] . W_fc[c][:] + b_fc[c]  (unchanged)
// ---------------------------------------------------------------------------
__global__ void __launch_bounds__(256) fc_gemm(
    const float* __restrict__ W_fc,
    const float* __restrict__ b_fc,
    float* __restrict__ out)
{
    __shared__ float As[8][128];
    __shared__ float Bs[8][128];

    const int m0 = blockIdx.x * 128;
    const int tid = threadIdx.x;
    const int tx = tid & 15;
    const int ty = tid >> 4;

    float acc[8][8];
#pragma unroll
    for (int i = 0; i < 8; i++)
#pragma unroll
        for (int j = 0; j < 8; j++) acc[i][j] = 0.0f;

    const int lr = tid >> 1;
    const int lk = (tid & 1) * 4;

    for (int k0 = 0; k0 < HH; k0 += 8) {
        {
            float4 v = *(const float4*)(g_hs + (size_t)(m0 + lr) * HH + k0 + lk);
            As[lk + 0][lr] = v.x; As[lk + 1][lr] = v.y;
            As[lk + 2][lr] = v.z; As[lk + 3][lr] = v.w;
        }
        {
            float4 v = *(const float4*)(W_fc + (size_t)lr * HH + k0 + lk);
            Bs[lk + 0][lr] = v.x; Bs[lk + 1][lr] = v.y;
            Bs[lk + 2][lr] = v.z; Bs[lk + 3][lr] = v.w;
        }
        __syncthreads();
#pragma unroll
        for (int k = 0; k < 8; k++) {
            float a[8], b[8];
            float4 a0 = *(const float4*)&As[k][ty * 4];
            float4 a1 = *(const float4*)&As[k][64 + ty * 4];
            float4 b0 = *(const float4*)&Bs[k][tx * 4];
            float4 b1 = *(const float4*)&Bs[k][64 + tx * 4];
            a[0]=a0.x; a[1]=a0.y; a[2]=a0.z; a[3]=a0.w;
            a[4]=a1.x; a[5]=a1.y; a[6]=a1.z; a[7]=a1.w;
            b[0]=b0.x; b[1]=b0.y; b[2]=b0.z; b[3]=b0.w;
            b[4]=b1.x; b[5]=b1.y; b[6]=b1.z; b[7]=b1.w;
#pragma unroll
            for (int i = 0; i < 8; i++)
#pragma unroll
                for (int j = 0; j < 8; j++)
                    acc[i][j] = fmaf(a[i], b[j], acc[i][j]);
        }
        __syncthreads();
    }

#pragma unroll
    for (int i = 0; i < 8; i++) {
        int m = m0 + (i >> 2) * 64 + ty * 4 + (i & 3);
        int bb = m & 63;
        int tt = m >> 6;
        size_t orow = ((size_t)bb * TT + tt) * CC;
#pragma unroll
        for (int j = 0; j < 8; j++) {
            int cc = (j >> 2) * 64 + tx * 4 + (j & 3);
            out[orow + cc] = acc[i][j] + b_fc[cc];
        }
    }
}

// ---------------------------------------------------------------------------
extern "C" void kernel_launch(void* const* d_in, const int* in_sizes, int n_in,
                              void* d_out, int out_size)
{
    const float* x    = (const float*)d_in[0];
    const float* W_ih = (const float*)d_in[1];
    const float* W_hh = (const float*)d_in[2];
    const float* b_ih = (const float*)d_in[3];
    const float* b_hh = (const float*)d_in[4];
    const float* W_fc = (const float*)d_in[5];
    const float* b_fc = (const float*)d_in[6];
    float* out = (float*)d_out;

    cudaFuncSetAttribute(lstm_recur,
                         cudaFuncAttributeMaxDynamicSharedMemorySize,
                         SMEM_RECUR);

    dim3 g1(4 * HH / 128, (BB * TT) / 128);   // (16, 256)
    gates_gemm<<<g1, 256>>>(x, W_ih, b_ih, b_hh);

    lstm_recur<<<128, 256, SMEM_RECUR>>>(W_hh);   // 128 CTAs, co-resident

    fc_gemm<<<(BB * TT) / 128, 256>>>(W_fc, b_fc, out);
}